// round 8
// baseline (speedup 1.0000x reference)
#include <cuda_runtime.h>
#include <cstdint>

#define TSTEPS 512
#define BATCH  64
#define HB     32          // half-batch stream size
#define IDIM   256
#define HDIM   2048
#define NMT    16          // h tiles (2048/128)
#define NKG    9           // 8 K-slices of W_hat + 1 for W_in
#define NCTA   (NMT*NKG)   // 144 CTAs co-resident
#define KSL    256
#define NT     128         // h per CTA tile
#define WPAD   260
#define APAD   260
#define NTHR   512
#define BH     (BATCH*HDIM)
#define HBH    (HB*HDIM)
#define SMEM_BYTES ((NT*WPAD + HB*APAD)*4)   // 166,400 B

__device__ float    g_state[3][BH];            // triple-buffered state [b][h]
__device__ float    g_part[2][3][NKG][HBH];    // [half][buf(t%3)][kg][b_local*HDIM+h]
__device__ unsigned g_pflag[2][NCTA];          // produce flags per half (monotonic)
__device__ unsigned g_fflag[2][NCTA];          // finalize flags per half (monotonic)

__device__ __forceinline__ void mma_tf32(float* c, const uint32_t* a, const uint32_t* b) {
    asm volatile(
        "mma.sync.aligned.m16n8k8.row.col.f32.tf32.tf32.f32 "
        "{%0,%1,%2,%3}, {%4,%5,%6,%7}, {%8,%9}, {%0,%1,%2,%3};\n"
        : "+f"(c[0]), "+f"(c[1]), "+f"(c[2]), "+f"(c[3])
        : "r"(a[0]), "r"(a[1]), "r"(a[2]), "r"(a[3]), "r"(b[0]), "r"(b[1]));
}
__device__ __forceinline__ uint32_t rna_tf32(float f) {
    uint32_t u; asm("cvt.rna.tf32.f32 %0, %1;" : "=r"(u) : "f"(f)); return u;
}
__device__ __forceinline__ void relstore(unsigned* p, unsigned v) {
    asm volatile("st.release.gpu.global.u32 [%0], %1;" :: "l"(p), "r"(v) : "memory");
}
__device__ __forceinline__ unsigned acqload(const unsigned* p) {
    unsigned v;
    asm volatile("ld.acquire.gpu.global.u32 %0, [%1];" : "=r"(v) : "l"(p) : "memory");
    return v;
}
__device__ __forceinline__ void poll(const unsigned* p, unsigned tgt) {
    while ((int)(acqload(p) - tgt) < 0) { }
}

__global__ void __launch_bounds__(NTHR, 1)
reservoir_kernel(const float* __restrict__ x,     // [T,B,I]
                 const float* __restrict__ s0,    // [B,H]
                 const float* __restrict__ Win,   // [H,I]
                 const float* __restrict__ What,  // [H,H]
                 float* __restrict__ out)         // [T,B,H]
{
    extern __shared__ float smem[];
    float* Ws = smem;                 // [NT][WPAD]  weight rows (n = h-local)
    float* As = smem + NT*WPAD;       // [HB][APAD]  A tile (reused per stream)

    const int c   = blockIdx.x;
    const int tid = threadIdx.x;
    const int mt  = c % NMT;
    const int kg  = c / NMT;           // 8 = input projection
    const int warp = tid >> 5, lane = tid & 31;
    const int gid  = lane >> 2, tig = lane & 3;
    const int wm   = (warp & 1) * 16;          // 2 warp-rows over M=32 (batch)
    const int wn   = (warp >> 1) * 16;         // 8 warp-cols over N=128 (h), 16 each

    const unsigned pb0 = *(volatile unsigned*)&g_pflag[0][c];
    const unsigned pb1 = *(volatile unsigned*)&g_pflag[1][c];
    const unsigned fb0 = *(volatile unsigned*)&g_fflag[0][c];
    const unsigned fb1 = *(volatile unsigned*)&g_fflag[1][c];

    // ---- one-time: weight slice -> SMEM (tf32 RNA) ----
    {
        const float* src; int stride;
        if (kg < 8) { src = What + (size_t)mt*NT*HDIM + (size_t)kg*KSL; stride = HDIM; }
        else        { src = Win  + (size_t)mt*NT*IDIM;                  stride = IDIM; }
        for (int i = tid; i < NT*64; i += NTHR) {
            int r = i >> 6, c4 = i & 63;
            float4 v = *(const float4*)(src + (size_t)r*stride + c4*4);
            uint4 u;
            u.x = rna_tf32(v.x); u.y = rna_tf32(v.y); u.z = rna_tf32(v.z); u.w = rna_tf32(v.w);
            *(uint4*)(Ws + r*WPAD + c4*4) = u;
        }
    }
    // ---- one-time: s0 -> state buffer 2 ----
    if (c < 64) {
        ((float4*)g_state[2])[c*512 + tid] = ((const float4*)s0)[c*512 + tid];
    }
    __syncthreads();
    if (tid == 0) relstore(&g_pflag[0][c], pb0 + 1);
    if (tid < NCTA) poll(&g_pflag[0][tid], pb0 + 1);
    __syncthreads();

    // finalize chunk bounds over [HB x NT] block (e = b_local*128 + h_local)
    // max chunk = ceil(4096/9) = 456 <= NTHR, so one element per thread
    const int e0 = (kg * (HB*NT)) / NKG;
    const int e1 = ((kg + 1) * (HB*NT)) / NKG;

    for (int t = 0; t < TSTEPS; ++t) {
        const int pbuf = t % 3;

        // ================= produce: stream h = 0, then 1 =================
        for (int h = 0; h < 2; ++h) {
            const unsigned ftgt = (h ? fb1 : fb0) + (unsigned)t;   // t=0 trivially true
            const unsigned ptgt = (h ? pb1 + 1 : pb0 + 2) + (unsigned)t;

            // wait on ALL finalizers of this half from step t-1
            if (kg < 8 && tid < NCTA) poll(&g_fflag[h][tid], ftgt);
            __syncthreads();

            // ---- A tile: state half-slice (or x_t half) -> regs -> SMEM ----
            const float* src = (kg < 8) ? (g_state[(t+2)%3] + (size_t)h*HB*HDIM + kg*KSL)
                                        : (x + (size_t)t*BATCH*IDIM + (size_t)h*HB*IDIM);
            const int stride = (kg < 8) ? HDIM : IDIM;
            float4 v[4];
            #pragma unroll
            for (int p = 0; p < 4; ++p) {
                int i = tid + p*NTHR, r = i >> 6, c4 = i & 63;
                v[p] = *(const float4*)(src + (size_t)r*stride + c4*4);
            }
            #pragma unroll
            for (int p = 0; p < 4; ++p) {
                int i = tid + p*NTHR, r = i >> 6, c4 = i & 63;
                uint4 u;
                u.x = rna_tf32(v[p].x); u.y = rna_tf32(v[p].y);
                u.z = rna_tf32(v[p].z); u.w = rna_tf32(v[p].w);
                *(uint4*)(As + r*APAD + c4*4) = u;
            }
            __syncthreads();

            // ---- MMA: D[32,128] = As[32,256] * Ws[128,256]^T, warp tile m16n16 ----
            float acc[2][4];
            #pragma unroll
            for (int ni = 0; ni < 2; ++ni)
                #pragma unroll
                for (int q = 0; q < 4; ++q) acc[ni][q] = 0.f;

            #pragma unroll 4
            for (int kk = 0; kk < KSL; kk += 8) {
                uint32_t a[4], b[2][2];
                const float* ap = As + (wm + gid)*APAD + kk + tig;
                a[0] = __float_as_uint(ap[0]);
                a[1] = __float_as_uint(ap[8*APAD]);
                a[2] = __float_as_uint(ap[4]);
                a[3] = __float_as_uint(ap[8*APAD + 4]);
                #pragma unroll
                for (int ni = 0; ni < 2; ++ni) {
                    const float* bp = Ws + (wn + ni*8 + gid)*WPAD + kk + tig;
                    b[ni][0] = __float_as_uint(bp[0]);
                    b[ni][1] = __float_as_uint(bp[4]);
                }
                #pragma unroll
                for (int ni = 0; ni < 2; ++ni)
                    mma_tf32(acc[ni], a, b[ni]);
            }
            __syncthreads();   // done reading As before next stream overwrites

            // ---- partial store [b_local][h] ----
            {
                float* dst = &g_part[h][pbuf][kg][0] + mt*NT;
                #pragma unroll
                for (int ni = 0; ni < 2; ++ni) {
                    const int row = wm + gid;
                    const int col = wn + ni*8 + tig*2;
                    *(float2*)(dst + (size_t)row*HDIM + col) =
                        make_float2(acc[ni][0], acc[ni][1]);
                    *(float2*)(dst + (size_t)(row+8)*HDIM + col) =
                        make_float2(acc[ni][2], acc[ni][3]);
                }
            }
            __syncthreads();
            if (tid == 0) relstore(&g_pflag[h][c], ptgt);
        }

        // ================= finalize: stream h = 0, then 1 =================
        for (int h = 0; h < 2; ++h) {
            const unsigned ptgt = (h ? pb1 + 1 : pb0 + 2) + (unsigned)t;
            // wait on ALL producers of this half from step t
            if (tid < NCTA) poll(&g_pflag[h][tid], ptgt);
            __syncthreads();

            {
                const float* P  = &g_part[h][pbuf][0][0];
                const float* sp = g_state[(t+2)%3];
                float*       sn = g_state[t%3];
                float*       op = out + (size_t)t*BH;

                const int e = e0 + tid;
                if (e < e1) {
                    const int bl = e >> 7;
                    const int off = bl*HDIM + mt*NT + (e & 127);
                    float s = P[off];
                    #pragma unroll
                    for (int k2 = 1; k2 < NKG; ++k2) s += P[(size_t)k2*HBH + off];
                    const int so = (h*HB + bl)*HDIM + mt*NT + (e & 127);
                    const float ns = 0.5f*(sp[so] + tanhf(s));
                    sn[so] = ns;
                    op[so] = ns;
                }
            }
            __syncthreads();
            if (tid == 0) relstore(&g_fflag[h][c], (h ? fb1 : fb0) + 1 + (unsigned)t);
        }
    }
}

extern "C" void kernel_launch(void* const* d_in, const int* in_sizes, int n_in,
                              void* d_out, int out_size)
{
    (void)in_sizes; (void)n_in; (void)out_size;
    const float* x    = (const float*)d_in[0];
    const float* s0   = (const float*)d_in[1];
    const float* Win  = (const float*)d_in[2];
    const float* What = (const float*)d_in[3];

    cudaFuncSetAttribute(reservoir_kernel,
                         cudaFuncAttributeMaxDynamicSharedMemorySize, SMEM_BYTES);
    reservoir_kernel<<<NCTA, NTHR, SMEM_BYTES>>>(x, s0, Win, What, (float*)d_out);
}

// round 10
// speedup vs baseline: 1.7057x; 1.7057x over previous
#include <cuda_runtime.h>
#include <cstdint>

#define TSTEPS 512
#define BATCH  64
#define HB     32          // half-batch stream size
#define IDIM   256
#define HDIM   2048
#define NMT    16          // h tiles (2048/128)
#define NKG    9           // 8 K-slices of W_hat + 1 for W_in
#define NCTA   (NMT*NKG)   // 144 CTAs co-resident
#define KSL    256
#define NT     128         // h per CTA tile
#define APAD   260
#define NTHR   256
#define BH     (BATCH*HDIM)
#define HBH    (HB*HDIM)
// SMEM: Wp (permuted weights) + single A buffer (R6 style)
#define WP_FLOATS (16*4*4*32*4)            // 32768
#define SMEM_BYTES ((WP_FLOATS + HB*APAD)*4)   // 164,352 B

__device__ float    g_state[3][BH];            // triple-buffered state [b][h]
__device__ float    g_part[2][3][NKG][HBH];    // [half][buf(t%3)][kg][b_local*HDIM+h]
__device__ unsigned g_pflag[2][NCTA];          // produce flags per half (monotonic)
__device__ unsigned g_fflag[2][NCTA];          // finalize flags per half (monotonic)

__device__ __forceinline__ void mma_tf32(float* c, const uint32_t* a, const uint32_t* b) {
    asm volatile(
        "mma.sync.aligned.m16n8k8.row.col.f32.tf32.tf32.f32 "
        "{%0,%1,%2,%3}, {%4,%5,%6,%7}, {%8,%9}, {%0,%1,%2,%3};\n"
        : "+f"(c[0]), "+f"(c[1]), "+f"(c[2]), "+f"(c[3])
        : "r"(a[0]), "r"(a[1]), "r"(a[2]), "r"(a[3]), "r"(b[0]), "r"(b[1]));
}
__device__ __forceinline__ uint32_t rna_tf32(float f) {
    uint32_t u; asm("cvt.rna.tf32.f32 %0, %1;" : "=r"(u) : "f"(f)); return u;
}
__device__ __forceinline__ void relstore(unsigned* p, unsigned v) {
    asm volatile("st.release.gpu.global.u32 [%0], %1;" :: "l"(p), "r"(v) : "memory");
}
__device__ __forceinline__ unsigned acqload(const unsigned* p) {
    unsigned v;
    asm volatile("ld.acquire.gpu.global.u32 %0, [%1];" : "=r"(v) : "l"(p) : "memory");
    return v;
}
__device__ __forceinline__ void poll(const unsigned* p, unsigned tgt) {
    while ((int)(acqload(p) - tgt) < 0) { }
}

__global__ void __launch_bounds__(NTHR, 1)
reservoir_kernel(const float* __restrict__ x,     // [T,B,I]
                 const float* __restrict__ s0,    // [B,H]
                 const float* __restrict__ Win,   // [H,I]
                 const float* __restrict__ What,  // [H,H]
                 float* __restrict__ out)         // [T,B,H]
{
    extern __shared__ float smem[];
    float* Wp = smem;                 // permuted weight fragments
    float* As = smem + WP_FLOATS;     // [HB][APAD] A tile (reused per stream)

    const int c   = blockIdx.x;
    const int tid = threadIdx.x;
    const int mt  = c % NMT;
    const int kg  = c / NMT;           // 8 = input projection
    const int warp = tid >> 5, lane = tid & 31;
    const int gid  = lane >> 2, tig = lane & 3;
    const int wm   = (warp & 1) * 16;          // 2 warp-rows over M=32 (batch)
    const int wc   = warp >> 1;                // 4 warp-cols over N=128 (h), 32 each

    const unsigned pb0 = *(volatile unsigned*)&g_pflag[0][c];
    const unsigned pb1 = *(volatile unsigned*)&g_pflag[1][c];
    const unsigned fb0 = *(volatile unsigned*)&g_fflag[0][c];
    const unsigned fb1 = *(volatile unsigned*)&g_fflag[1][c];

    // ---- one-time: weight slice -> SMEM in mma-fragment-permuted order ----
    // Wp float4 index (p, wc, ni, lane): floats f=0..3 hold W[n][16p+4f+tig],
    // n = wc*32 + ni*8 + gid, lane = gid*4 + tig.   (validated in R7)
    {
        const float* src; int stride;
        if (kg < 8) { src = What + (size_t)mt*NT*HDIM + (size_t)kg*KSL; stride = HDIM; }
        else        { src = Win  + (size_t)mt*NT*IDIM;                  stride = IDIM; }
        for (int i = tid; i < NT*64; i += NTHR) {
            int r = i >> 6, q = i & 63;                // row r, k = 4q..4q+3
            float4 v = *(const float4*)(src + (size_t)r*stride + q*4);
            float* dst = Wp
                + ((((q >> 2)*4 + (r >> 5))*4 + ((r >> 3) & 3))*32 + (r & 7)*4)*4
                + (q & 3);
            dst[0]  = __uint_as_float(rna_tf32(v.x));
            dst[4]  = __uint_as_float(rna_tf32(v.y));
            dst[8]  = __uint_as_float(rna_tf32(v.z));
            dst[12] = __uint_as_float(rna_tf32(v.w));
        }
    }
    // ---- one-time: s0 -> state buffer 2 ----
    if (c < 128) {
        ((float4*)g_state[2])[c*256 + tid] = ((const float4*)s0)[c*256 + tid];
    }
    __syncthreads();
    if (tid == 0) relstore(&g_pflag[0][c], pb0 + 1);
    if (tid < NCTA) poll(&g_pflag[0][tid], pb0 + 1);
    __syncthreads();

    // finalize chunk bounds over [HB x NT] block (e = b_local*128 + h_local)
    const int e0 = (kg * (HB*NT)) / NKG;
    const int e1 = ((kg + 1) * (HB*NT)) / NKG;

    for (int t = 0; t < TSTEPS; ++t) {
        const int pbuf = t % 3;

        // ================= produce: stream h = 0, then 1 (R6 structure) ====
        for (int h = 0; h < 2; ++h) {
            const unsigned ftgt = (h ? fb1 : fb0) + (unsigned)t;   // t=0 trivially true
            const unsigned ptgt = (h ? pb1 + 1 : pb0 + 2) + (unsigned)t;

            // wait on ALL finalizers of this half from step t-1
            if (kg < 8 && tid < NCTA) poll(&g_fflag[h][tid], ftgt);
            __syncthreads();

            // ---- A tile: state half-slice (or x_t half) -> regs -> SMEM ----
            const float* src = (kg < 8) ? (g_state[(t+2)%3] + (size_t)h*HB*HDIM + kg*KSL)
                                        : (x + (size_t)t*BATCH*IDIM + (size_t)h*HB*IDIM);
            const int stride = (kg < 8) ? HDIM : IDIM;
            float4 v[8];
            #pragma unroll
            for (int p = 0; p < 8; ++p) {
                int i = tid + p*NTHR, r = i >> 6, c4 = i & 63;
                v[p] = *(const float4*)(src + (size_t)r*stride + c4*4);
            }
            #pragma unroll
            for (int p = 0; p < 8; ++p) {
                int i = tid + p*NTHR, r = i >> 6, c4 = i & 63;
                uint4 u;
                u.x = rna_tf32(v[p].x); u.y = rna_tf32(v[p].y);
                u.z = rna_tf32(v[p].z); u.w = rna_tf32(v[p].w);
                *(uint4*)(As + r*APAD + c4*4) = u;
            }
            __syncthreads();

            // ---- MMA: D[32,128] = As[32,256] * Wp^T (R7 loop, validated) ----
            float acc[4][4];
            #pragma unroll
            for (int ni = 0; ni < 4; ++ni)
                #pragma unroll
                for (int q = 0; q < 4; ++q) acc[ni][q] = 0.f;

            #pragma unroll 4
            for (int p = 0; p < 16; ++p) {
                uint4 b4[4];
                #pragma unroll
                for (int ni = 0; ni < 4; ++ni)
                    b4[ni] = *(const uint4*)(Wp + (((p*4 + wc)*4 + ni)*32 + lane)*4);

                const float* ap = As + (wm + gid)*APAD + p*16 + tig;
                uint32_t a0[4], a1[4];
                a0[0] = __float_as_uint(ap[0]);
                a0[1] = __float_as_uint(ap[8*APAD]);
                a0[2] = __float_as_uint(ap[4]);
                a0[3] = __float_as_uint(ap[8*APAD + 4]);
                a1[0] = __float_as_uint(ap[8]);
                a1[1] = __float_as_uint(ap[8*APAD + 8]);
                a1[2] = __float_as_uint(ap[12]);
                a1[3] = __float_as_uint(ap[8*APAD + 12]);

                #pragma unroll
                for (int ni = 0; ni < 4; ++ni) {
                    uint32_t b0[2] = { b4[ni].x, b4[ni].y };
                    mma_tf32(acc[ni], a0, b0);
                }
                #pragma unroll
                for (int ni = 0; ni < 4; ++ni) {
                    uint32_t b1[2] = { b4[ni].z, b4[ni].w };
                    mma_tf32(acc[ni], a1, b1);
                }
            }
            __syncthreads();   // done reading As before next stream overwrites

            // ---- partial store [b_local][h] ----
            {
                float* dst = &g_part[h][pbuf][kg][0] + mt*NT;
                #pragma unroll
                for (int ni = 0; ni < 4; ++ni) {
                    const int row = wm + gid;
                    const int col = wc*32 + ni*8 + tig*2;
                    *(float2*)(dst + (size_t)row*HDIM + col) =
                        make_float2(acc[ni][0], acc[ni][1]);
                    *(float2*)(dst + (size_t)(row+8)*HDIM + col) =
                        make_float2(acc[ni][2], acc[ni][3]);
                }
            }
            __syncthreads();
            if (tid == 0) relstore(&g_pflag[h][c], ptgt);
        }

        // ================= finalize: stream h = 0, then 1 (R6 verbatim) ====
        for (int h = 0; h < 2; ++h) {
            const unsigned ptgt = (h ? pb1 + 1 : pb0 + 2) + (unsigned)t;
            // wait on ALL producers of this half from step t
            if (tid < NCTA) poll(&g_pflag[h][tid], ptgt);
            __syncthreads();

            {
                const float* P  = &g_part[h][pbuf][0][0];
                const float* sp = g_state[(t+2)%3];
                float*       sn = g_state[t%3];
                float*       op = out + (size_t)t*BH;

                int e = e0 + tid;
                if (e < e1) {
                    const int bl = e >> 7;
                    const int off = bl*HDIM + mt*NT + (e & 127);
                    float s = P[off];
                    #pragma unroll
                    for (int k2 = 1; k2 < NKG; ++k2) s += P[(size_t)k2*HBH + off];
                    const int so = (h*HB + bl)*HDIM + mt*NT + (e & 127);
                    const float ns = 0.5f*(sp[so] + tanhf(s));
                    sn[so] = ns;
                    op[so] = ns;
                }
                e += NTHR;
                if (e < e1) {
                    const int bl = e >> 7;
                    const int off = bl*HDIM + mt*NT + (e & 127);
                    float s = P[off];
                    #pragma unroll
                    for (int k2 = 1; k2 < NKG; ++k2) s += P[(size_t)k2*HBH + off];
                    const int so = (h*HB + bl)*HDIM + mt*NT + (e & 127);
                    const float ns = 0.5f*(sp[so] + tanhf(s));
                    sn[so] = ns;
                    op[so] = ns;
                }
            }
            __syncthreads();
            if (tid == 0) relstore(&g_fflag[h][c], (h ? fb1 : fb0) + 1 + (unsigned)t);
        }
    }
}

extern "C" void kernel_launch(void* const* d_in, const int* in_sizes, int n_in,
                              void* d_out, int out_size)
{
    (void)in_sizes; (void)n_in; (void)out_size;
    const float* x    = (const float*)d_in[0];
    const float* s0   = (const float*)d_in[1];
    const float* Win  = (const float*)d_in[2];
    const float* What = (const float*)d_in[3];

    cudaFuncSetAttribute(reservoir_kernel,
                         cudaFuncAttributeMaxDynamicSharedMemorySize, SMEM_BYTES);
    reservoir_kernel<<<NCTA, NTHR, SMEM_BYTES>>>(x, s0, Win, What, (float*)d_out);
}